// round 7
// baseline (speedup 1.0000x reference)
#include <cuda_runtime.h>
#include <cstdint>

// v, out: [8, 4096, 16, 64] f32 ; w: [1, 16, 127]
// offset(b,s,h,e) = ((b*4096 + s)*16 + h)*64 + e ; s = s1*64 + s2
#define SSTR 1024     // floats between consecutive s rows
#define NW   127

// Block = (b, h, e-half). Grid 256, 256 threads (8 warps).
// Lane geometry: so = l>>3 (s-row offset), e4 = l&7 (float4 within the 128B
// e-half) -> every LDG.128/STG.128 covers 4 consecutive s-rows x 128B = 4 full
// cache lines.
// v5: software-pipelined f-pass — next tile's 16 DRAM loads are issued before
// the current tile's u-pass (L1 re-read + shuffles), so DRAM always has ~16
// loads/warp in flight. rv/ru reuse f_sh/u_sh (smem 33KB -> 17KB).
__global__ __launch_bounds__(256, 2)
void fftbias2d_v5(const float* __restrict__ v,
                  const float* __restrict__ wg,
                  float* __restrict__ out) {
    const int bid = blockIdx.x;
    const int eh  = bid & 1;                 // e-half (32 floats)
    const int h   = (bid >> 1) & 15;
    const int b   = bid >> 5;

    const int t  = threadIdx.x;
    const int w  = t >> 5;                   // warp 0..7
    const int l  = t & 31;
    const int so = l >> 3;                   // 0..3
    const int e4 = l & 7;                    // 0..7

    __shared__ float w_ext[128];
    __shared__ __align__(16) float4 f_sh[64][8];   // f[s2][e4] -> later RxV
    __shared__ __align__(16) float4 u_sh[64][8];   // u[s1][e4] -> later RxU

    // K[j][s] = w_ext[j + 64 - s], index in [1,127]; w_ext[127] aliases w[0].
    if (t < NW)  w_ext[t]  = wg[h * NW + t];
    if (t == NW) w_ext[NW] = wg[h * NW];

    const float* vb = v + (size_t)b * 4096 * SSTR + h * 64 + eh * 32 + e4 * 4;

    // ---------------- Phase 1: pipelined tile loop over s1 groups of 8 -----
    // f: warp owns s2 quads (s2a, s2a+32), reg accumulators, 16 loads/tile.
    // u: warp owns s1 = 8*tile + w, re-reads the (L1-hot) tile, 2 shfl rounds.
    const int s2a = 4 * w + so;

    float4 f0 = make_float4(0.f, 0.f, 0.f, 0.f);
    float4 f1 = make_float4(0.f, 0.f, 0.f, 0.f);
    float4 A[8], C[8];

    // preload tile 0
    #pragma unroll
    for (int i = 0; i < 8; ++i) {
        const float* r = vb + (size_t)(i * 64) * SSTR;
        A[i] = *(const float4*)(r + (size_t)s2a * SSTR);
        C[i] = *(const float4*)(r + (size_t)(s2a + 32) * SSTR);
    }

    #pragma unroll
    for (int tile = 0; tile < 8; ++tile) {
        // consume current tile (loads issued one tile ago)
        #pragma unroll
        for (int i = 0; i < 8; ++i) {
            f0.x += A[i].x; f0.y += A[i].y; f0.z += A[i].z; f0.w += A[i].w;
            f1.x += C[i].x; f1.y += C[i].y; f1.z += C[i].z; f1.w += C[i].w;
        }
        // prefetch next tile's 16 DRAM loads before the u-pass
        if (tile < 7) {
            #pragma unroll
            for (int i = 0; i < 8; ++i) {
                const float* r = vb + (size_t)(((tile + 1) * 8 + i) * 64) * SSTR;
                A[i] = *(const float4*)(r + (size_t)s2a * SSTR);
                C[i] = *(const float4*)(r + (size_t)(s2a + 32) * SSTR);
            }
        }
        // u-pass: s1 = 8*tile + w, all 64 s2 (16 quads) — tile is L1-hot
        {
            const float* r = vb + (size_t)((tile * 8 + w) * 64 + so) * SSTR;
            float4 ua = make_float4(0.f, 0.f, 0.f, 0.f);
            #pragma unroll
            for (int q = 0; q < 16; ++q) {
                const float4 a = *(const float4*)(r + (size_t)(4 * q) * SSTR);
                ua.x += a.x; ua.y += a.y; ua.z += a.z; ua.w += a.w;
            }
            ua.x += __shfl_xor_sync(0xffffffffu, ua.x, 8);
            ua.y += __shfl_xor_sync(0xffffffffu, ua.y, 8);
            ua.z += __shfl_xor_sync(0xffffffffu, ua.z, 8);
            ua.w += __shfl_xor_sync(0xffffffffu, ua.w, 8);
            ua.x += __shfl_xor_sync(0xffffffffu, ua.x, 16);
            ua.y += __shfl_xor_sync(0xffffffffu, ua.y, 16);
            ua.z += __shfl_xor_sync(0xffffffffu, ua.z, 16);
            ua.w += __shfl_xor_sync(0xffffffffu, ua.w, 16);
            if (l < 8) u_sh[tile * 8 + w][l] = ua;
        }
    }
    f_sh[s2a     ][e4] = f0;
    f_sh[s2a + 32][e4] = f1;
    __syncthreads();

    // ---------------- Phase 2: RxV[j] = sum_s K[j,s] f[s]; same for u ------
    // warp = one e4 slice (broadcast LDS); lane = j, handles j and j+32.
    {
        float4 rv0 = make_float4(0.f,0.f,0.f,0.f), rv1 = rv0;
        float4 ru0 = rv0, ru1 = rv0;
        #pragma unroll 4
        for (int s = 0; s < 64; ++s) {
            const float4 fv = f_sh[s][w];           // broadcast
            const float4 uv = u_sh[s][w];           // broadcast
            const float wa = w_ext[l + 64 - s];     // j = l
            const float wb = w_ext[l + 96 - s];     // j = l + 32
            rv0.x += wa * fv.x; rv0.y += wa * fv.y; rv0.z += wa * fv.z; rv0.w += wa * fv.w;
            rv1.x += wb * fv.x; rv1.y += wb * fv.y; rv1.z += wb * fv.z; rv1.w += wb * fv.w;
            ru0.x += wa * uv.x; ru0.y += wa * uv.y; ru0.z += wa * uv.z; ru0.w += wa * uv.w;
            ru1.x += wb * uv.x; ru1.y += wb * uv.y; ru1.z += wb * uv.z; ru1.w += wb * uv.w;
        }
        __syncthreads();                            // done reading f/u
        f_sh[l     ][w] = rv0;                      // f_sh now holds RxV
        f_sh[l + 32][w] = rv1;
        u_sh[l     ][w] = ru0;                      // u_sh now holds RxU
        u_sh[l + 32][w] = ru1;
    }
    __syncthreads();

    // ---------------- Phase 3: out[s1*64+s2] = RxV[s2] + RxU[s1] -----------
    // Same 4-line-per-store geometry: warp stores s2 quads {s2a, s2a+32}.
    {
        const float4 rva = f_sh[s2a     ][e4];
        const float4 rvb = f_sh[s2a + 32][e4];
        float* ob = out + (size_t)b * 4096 * SSTR + h * 64 + eh * 32 + e4 * 4;
        #pragma unroll 4
        for (int s1 = 0; s1 < 64; ++s1) {
            const float4 ru = u_sh[s1][e4];         // broadcast
            float* r = ob + (size_t)(s1 * 64) * SSTR;
            float4 o0, o1;
            o0.x = rva.x + ru.x; o0.y = rva.y + ru.y;
            o0.z = rva.z + ru.z; o0.w = rva.w + ru.w;
            o1.x = rvb.x + ru.x; o1.y = rvb.y + ru.y;
            o1.z = rvb.z + ru.z; o1.w = rvb.w + ru.w;
            *(float4*)(r + (size_t)s2a * SSTR)        = o0;
            *(float4*)(r + (size_t)(s2a + 32) * SSTR) = o1;
        }
    }
}

extern "C" void kernel_launch(void* const* d_in, const int* in_sizes, int n_in,
                              void* d_out, int out_size) {
    (void)in_sizes; (void)n_in; (void)out_size;
    const float* v = (const float*)d_in[0];
    const float* w = (const float*)d_in[1];
    float* o = (float*)d_out;
    fftbias2d_v5<<<256, 256>>>(v, w, o);
}

// round 8
// speedup vs baseline: 1.2243x; 1.2243x over previous
#include <cuda_runtime.h>
#include <cstdint>

// v, out: [8, 4096, 16, 64] f32 ; w: [1, 16, 127]
// offset(b,s,h,e) = ((b*4096 + s)*16 + h)*64 + e ; s = s1*64 + s2
#define SSTR   1024
#define NW     127
#define STAGES 8
#define ROWB   144                 // stage row: 128B data + 16B pad (bank cycling)
#define STAGEB (64 * ROWB)         // 9216 B per stage
// dynamic smem: stages | f_sh[64][8]f4 | u_sh[64][8]f4 | w_ext[128]
#define SM_FSH  (STAGES * STAGEB)
#define SM_USH  (SM_FSH + 64 * 8 * 16)
#define SM_WEXT (SM_USH + 64 * 8 * 16)
#define SM_TOT  (SM_WEXT + 512)

__device__ __forceinline__ void cpasync16(uint32_t dst, const void* src) {
    asm volatile("cp.async.cg.shared.global [%0], [%1], 16;\n"
                 :: "r"(dst), "l"(src));
}
__device__ __forceinline__ void cpcommit() {
    asm volatile("cp.async.commit_group;\n");
}
__device__ __forceinline__ void cpwait6() {
    asm volatile("cp.async.wait_group 6;\n");
}

extern __shared__ char smdyn[];

__global__ __launch_bounds__(256)
void fftbias2d_v6(const float* __restrict__ v,
                  const float* __restrict__ wg,
                  float* __restrict__ out) {
    const int bid = blockIdx.x;
    const int eh  = bid & 1;                  // e-half (32 floats)
    const int h   = (bid >> 1) & 15;
    const int b   = bid >> 5;

    const int t  = threadIdx.x;
    const int w  = t >> 5;                    // warp 0..7
    const int l  = t & 31;
    const int lr  = l >> 3;                   // cp.async row-within-4
    const int e4l = l & 7;                    // cp.async e4 lane

    float4* f_sh  = (float4*)(smdyn + SM_FSH);   // [s2][e4]
    float4* u_sh  = (float4*)(smdyn + SM_USH);   // [s1][e4]
    float*  w_ext = (float*)(smdyn + SM_WEXT);

    // K[j][s] = w_ext[j + 64 - s], index in [1,127]; w_ext[127] aliases w[0].
    if (t < NW)  w_ext[t]  = wg[h * NW + t];
    if (t == NW) w_ext[NW] = wg[h * NW];

    const float* vb = v + (size_t)b * 4096 * SSTR + h * 64 + eh * 32;
    const uint32_t stg_s = (uint32_t)__cvta_generic_to_shared(smdyn);

    // ---- cp.async producer: chunk s1 = 64 s2-rows x 128B, warp w loads rows
    // w*8 .. w*8+8 (two 4-row x 8-lane warp-ops = 4 full lines each).
    #define ISSUE(s1_) {                                                      \
        const int _s1 = (s1_);                                                \
        const uint32_t _base = stg_s + (_s1 & (STAGES - 1)) * STAGEB;         \
        const int _r0 = w * 8 + lr;                                           \
        cpasync16(_base + _r0 * ROWB + e4l * 16,                              \
                  vb + (size_t)(_s1 * 64 + _r0) * SSTR + e4l * 4);            \
        const int _r1 = _r0 + 4;                                              \
        cpasync16(_base + _r1 * ROWB + e4l * 16,                              \
                  vb + (size_t)(_s1 * 64 + _r1) * SSTR + e4l * 4);            \
        cpcommit();                                                           \
    }

    #pragma unroll
    for (int s1 = 0; s1 < STAGES - 1; ++s1) ISSUE(s1);

    // ---- consumer: warp w owns e4-column w; lane l owns s2 = {l, l+32}.
    // column reads at l*144 + w*16: bank16 = (l*9+w) mod 8 = (l+w) mod 8 ->
    // conflict-free.
    float4 fa0 = make_float4(0.f, 0.f, 0.f, 0.f);
    float4 fa1 = make_float4(0.f, 0.f, 0.f, 0.f);

    for (int s1 = 0; s1 < 64; ++s1) {
        cpwait6();                    // groups 0..s1 complete (7+s1 committed)
        __syncthreads();              // cross-warp visibility of stage s1
        const char* buf = smdyn + (s1 & (STAGES - 1)) * STAGEB;
        const float4 a0 = *(const float4*)(buf + l * ROWB + w * 16);
        const float4 a1 = *(const float4*)(buf + (l + 32) * ROWB + w * 16);
        fa0.x += a0.x; fa0.y += a0.y; fa0.z += a0.z; fa0.w += a0.w;
        fa1.x += a1.x; fa1.y += a1.y; fa1.z += a1.z; fa1.w += a1.w;
        // u[s1][e4=w] = sum over all 64 s2 -> full-warp float4 reduce
        float4 us;
        us.x = a0.x + a1.x; us.y = a0.y + a1.y;
        us.z = a0.z + a1.z; us.w = a0.w + a1.w;
        #pragma unroll
        for (int m = 1; m <= 16; m <<= 1) {
            us.x += __shfl_xor_sync(0xffffffffu, us.x, m);
            us.y += __shfl_xor_sync(0xffffffffu, us.y, m);
            us.z += __shfl_xor_sync(0xffffffffu, us.z, m);
            us.w += __shfl_xor_sync(0xffffffffu, us.w, m);
        }
        if (l == 0) u_sh[s1 * 8 + w] = us;
        // keep the pipeline full; empty commits in the tail keep the
        // group-count invariant for cpwait6
        if (s1 + STAGES - 1 < 64) ISSUE(s1 + STAGES - 1) else cpcommit();
    }
    f_sh[l * 8 + w]        = fa0;     // f[s2=l][e4=w]
    f_sh[(l + 32) * 8 + w] = fa1;
    __syncthreads();

    // ---- Phase 2: RxV[j] = sum_s K[j,s] f[s]; RxU likewise. warp = e4 slice
    // (broadcast LDS); lane = j, handles j and j+32.
    {
        float4 rv0 = make_float4(0.f,0.f,0.f,0.f), rv1 = rv0;
        float4 ru0 = rv0, ru1 = rv0;
        #pragma unroll 4
        for (int s = 0; s < 64; ++s) {
            const float4 fv = f_sh[s * 8 + w];
            const float4 uv = u_sh[s * 8 + w];
            const float wa = w_ext[l + 64 - s];
            const float wb = w_ext[l + 96 - s];
            rv0.x += wa * fv.x; rv0.y += wa * fv.y; rv0.z += wa * fv.z; rv0.w += wa * fv.w;
            rv1.x += wb * fv.x; rv1.y += wb * fv.y; rv1.z += wb * fv.z; rv1.w += wb * fv.w;
            ru0.x += wa * uv.x; ru0.y += wa * uv.y; ru0.z += wa * uv.z; ru0.w += wa * uv.w;
            ru1.x += wb * uv.x; ru1.y += wb * uv.y; ru1.z += wb * uv.z; ru1.w += wb * uv.w;
        }
        __syncthreads();
        f_sh[l * 8 + w]        = rv0;   // f_sh now RxV
        f_sh[(l + 32) * 8 + w] = rv1;
        u_sh[l * 8 + w]        = ru0;   // u_sh now RxU
        u_sh[(l + 32) * 8 + w] = ru1;
    }
    __syncthreads();

    // ---- Phase 3: out[s1*64+s2] = RxV[s2] + RxU[s1]; 4-full-line STG.128.
    {
        const int so  = l >> 3;
        const int e4p = l & 7;
        const int s2a = 4 * w + so;
        const float4 rva = f_sh[s2a * 8 + e4p];
        const float4 rvb = f_sh[(s2a + 32) * 8 + e4p];
        float* ob = out + (size_t)b * 4096 * SSTR + h * 64 + eh * 32 + e4p * 4;
        #pragma unroll 4
        for (int s1 = 0; s1 < 64; ++s1) {
            const float4 ru = u_sh[s1 * 8 + e4p];
            float* r = ob + (size_t)(s1 * 64) * SSTR;
            float4 o0, o1;
            o0.x = rva.x + ru.x; o0.y = rva.y + ru.y;
            o0.z = rva.z + ru.z; o0.w = rva.w + ru.w;
            o1.x = rvb.x + ru.x; o1.y = rvb.y + ru.y;
            o1.z = rvb.z + ru.z; o1.w = rvb.w + ru.w;
            *(float4*)(r + (size_t)s2a * SSTR)        = o0;
            *(float4*)(r + (size_t)(s2a + 32) * SSTR) = o1;
        }
    }
}

extern "C" void kernel_launch(void* const* d_in, const int* in_sizes, int n_in,
                              void* d_out, int out_size) {
    (void)in_sizes; (void)n_in; (void)out_size;
    const float* v = (const float*)d_in[0];
    const float* w = (const float*)d_in[1];
    float* o = (float*)d_out;
    cudaFuncSetAttribute(fftbias2d_v6,
                         cudaFuncAttributeMaxDynamicSharedMemorySize, SM_TOT);
    fftbias2d_v6<<<256, 256, SM_TOT>>>(v, w, o);
}

// round 9
// speedup vs baseline: 1.3623x; 1.1128x over previous
#include <cuda_runtime.h>
#include <cstdint>

// v, out: [8, 4096, 16, 64] f32 ; w: [1, 16, 127]
// offset(b,s,h,e) = ((b*4096 + s)*16 + h)*64 + e ; s = s1*64 + s2
#define SSTR   1024
#define NW     127
#define STAGES 8
#define WSTG   1024                 // bytes per warp per stage (8 rows x 128B)
#define STAGEB (8 * WSTG)           // 8 KB per stage

__device__ __forceinline__ void cpasync16(uint32_t dst, const void* src) {
    asm volatile("cp.async.cg.shared.global [%0], [%1], 16;\n"
                 :: "r"(dst), "l"(src));
}
__device__ __forceinline__ void cpcommit() {
    asm volatile("cp.async.commit_group;\n");
}
__device__ __forceinline__ void cpwait6() {
    asm volatile("cp.async.wait_group 6;\n");
}

extern __shared__ char smdyn[];     // STAGES * STAGEB = 64 KB stage ring

// Block = (b, h, e-half). Grid 256, 256 threads (8 warps).
// Warp w is a self-contained pipeline over rows s2 in [8w, 8w+8): it issues
// its own cp.async (lane reads exactly what it loaded -> no per-stage
// barriers), accumulates f in registers, and produces an 8-row u-partial per
// stage via a 2-round shuffle. Cross-warp u combine runs once per 8 stages
// behind a single barrier (double-parity ring).
__global__ __launch_bounds__(256, 2)
void fftbias2d_v7(const float* __restrict__ v,
                  const float* __restrict__ wg,
                  float* __restrict__ out) {
    const int bid = blockIdx.x;
    const int eh  = bid & 1;                 // e-half (32 floats)
    const int h   = (bid >> 1) & 15;
    const int b   = bid >> 5;

    const int t  = threadIdx.x;
    const int w  = t >> 5;                   // warp 0..7
    const int l  = t & 31;
    const int rp = l >> 3;                   // row-in-4 (0..3)
    const int e4 = l & 7;                    // float4 within 128B e-half

    __shared__ __align__(16) float4 u_part[16][8][8];  // [ring][w][e4] 16 KB
    __shared__ __align__(16) float4 f_sh[64][8];       // f[s2][e4] -> RxV
    __shared__ __align__(16) float4 u_sh[64][8];       // u[s1][e4] -> RxU
    __shared__ float w_ext[128];

    // K[j][s] = w_ext[j + 64 - s], index in [1,127]; w_ext[127] aliases w[0].
    if (t < NW)  w_ext[t]  = wg[h * NW + t];
    if (t == NW) w_ext[NW] = wg[h * NW];
    __syncthreads();                         // w_ext ready before phase 2

    const float* vb = v + (size_t)b * 4096 * SSTR + h * 64 + eh * 32;
    const uint32_t stg = (uint32_t)__cvta_generic_to_shared(smdyn);

    // Per-warp stage fill: lane l loads rows (8w+rp, 8w+rp+4) at col e4.
    // smem: warp region is linear, dst = l*16 (and +512) -> conflict-free.
    #define ISSUE(s1_) {                                                     \
        const uint32_t _d = stg + ((s1_) & 7) * STAGEB + w * WSTG + l * 16;  \
        const float* _s = vb + (size_t)((s1_) * 64 + 8 * w + rp) * SSTR      \
                             + e4 * 4;                                       \
        cpasync16(_d,       _s);                                             \
        cpasync16(_d + 512, _s + 4 * SSTR);                                  \
        cpcommit();                                                          \
    }

    #pragma unroll
    for (int s1 = 0; s1 < STAGES - 1; ++s1) ISSUE(s1);

    float4 fa0 = make_float4(0.f, 0.f, 0.f, 0.f);
    float4 fa1 = make_float4(0.f, 0.f, 0.f, 0.f);

    for (int grp = 0; grp < 8; ++grp) {
        #pragma unroll
        for (int i = 0; i < 8; ++i) {
            const int s1 = grp * 8 + i;
            cpwait6();                        // stage s1 (this warp's part) done
            const char* buf = smdyn + (s1 & 7) * STAGEB + w * WSTG + l * 16;
            const float4 a0 = *(const float4*)buf;
            const float4 a1 = *(const float4*)(buf + 512);
            fa0.x += a0.x; fa0.y += a0.y; fa0.z += a0.z; fa0.w += a0.w;
            fa1.x += a1.x; fa1.y += a1.y; fa1.z += a1.z; fa1.w += a1.w;
            // u-partial over this warp's 8 rows (reduce over rp: 2 rounds)
            float4 us;
            us.x = a0.x + a1.x; us.y = a0.y + a1.y;
            us.z = a0.z + a1.z; us.w = a0.w + a1.w;
            us.x += __shfl_xor_sync(0xffffffffu, us.x, 8);
            us.y += __shfl_xor_sync(0xffffffffu, us.y, 8);
            us.z += __shfl_xor_sync(0xffffffffu, us.z, 8);
            us.w += __shfl_xor_sync(0xffffffffu, us.w, 8);
            us.x += __shfl_xor_sync(0xffffffffu, us.x, 16);
            us.y += __shfl_xor_sync(0xffffffffu, us.y, 16);
            us.z += __shfl_xor_sync(0xffffffffu, us.z, 16);
            us.w += __shfl_xor_sync(0xffffffffu, us.w, 16);
            if (l < 8) u_part[s1 & 15][w][l] = us;
            if (s1 + STAGES - 1 < 64) ISSUE(s1 + STAGES - 1) else cpcommit();
        }
        __syncthreads();                      // group's u_part complete
        if (t < 64) {                         // fold 8 warp-partials
            const int s1g = grp * 8 + (t >> 3);
            const int eq  = t & 7;
            float4 a = make_float4(0.f, 0.f, 0.f, 0.f);
            #pragma unroll
            for (int w2 = 0; w2 < 8; ++w2) {
                const float4 p = u_part[s1g & 15][w2][eq];
                a.x += p.x; a.y += p.y; a.z += p.z; a.w += p.w;
            }
            u_sh[s1g][eq] = a;
        }
        // next group writes the other ring parity -> no second barrier
    }
    f_sh[8 * w + rp    ][e4] = fa0;
    f_sh[8 * w + rp + 4][e4] = fa1;
    __syncthreads();

    // ---- Phase 2: RxV[j] = sum_s K[j,s] f[s]; RxU likewise. warp = e4 slice
    // (broadcast LDS); lane = j, handles j and j+32.
    {
        float4 rv0 = make_float4(0.f,0.f,0.f,0.f), rv1 = rv0;
        float4 ru0 = rv0, ru1 = rv0;
        #pragma unroll 4
        for (int s = 0; s < 64; ++s) {
            const float4 fv = f_sh[s][w];
            const float4 uv = u_sh[s][w];
            const float wa = w_ext[l + 64 - s];
            const float wb = w_ext[l + 96 - s];
            rv0.x += wa * fv.x; rv0.y += wa * fv.y; rv0.z += wa * fv.z; rv0.w += wa * fv.w;
            rv1.x += wb * fv.x; rv1.y += wb * fv.y; rv1.z += wb * fv.z; rv1.w += wb * fv.w;
            ru0.x += wa * uv.x; ru0.y += wa * uv.y; ru0.z += wa * uv.z; ru0.w += wa * uv.w;
            ru1.x += wb * uv.x; ru1.y += wb * uv.y; ru1.z += wb * uv.z; ru1.w += wb * uv.w;
        }
        __syncthreads();
        f_sh[l     ][w] = rv0;               // f_sh now holds RxV
        f_sh[l + 32][w] = rv1;
        u_sh[l     ][w] = ru0;               // u_sh now holds RxU
        u_sh[l + 32][w] = ru1;
    }
    __syncthreads();

    // ---- Phase 3: out[s1*64+s2] = RxV[s2] + RxU[s1]; 4-full-line STG.128.
    {
        const int s2a = 4 * w + rp;
        const float4 rva = f_sh[s2a     ][e4];
        const float4 rvb = f_sh[s2a + 32][e4];
        float* ob = out + (size_t)b * 4096 * SSTR + h * 64 + eh * 32 + e4 * 4;
        #pragma unroll 4
        for (int s1 = 0; s1 < 64; ++s1) {
            const float4 ru = u_sh[s1][e4];  // broadcast
            float* r = ob + (size_t)(s1 * 64) * SSTR;
            float4 o0, o1;
            o0.x = rva.x + ru.x; o0.y = rva.y + ru.y;
            o0.z = rva.z + ru.z; o0.w = rva.w + ru.w;
            o1.x = rvb.x + ru.x; o1.y = rvb.y + ru.y;
            o1.z = rvb.z + ru.z; o1.w = rvb.w + ru.w;
            *(float4*)(r + (size_t)s2a * SSTR)        = o0;
            *(float4*)(r + (size_t)(s2a + 32) * SSTR) = o1;
        }
    }
}

extern "C" void kernel_launch(void* const* d_in, const int* in_sizes, int n_in,
                              void* d_out, int out_size) {
    (void)in_sizes; (void)n_in; (void)out_size;
    const float* v = (const float*)d_in[0];
    const float* w = (const float*)d_in[1];
    float* o = (float*)d_out;
    cudaFuncSetAttribute(fftbias2d_v7,
                         cudaFuncAttributeMaxDynamicSharedMemorySize,
                         STAGES * STAGEB);
    fftbias2d_v7<<<256, 256, STAGES * STAGEB>>>(v, w, o);
}

// round 10
// speedup vs baseline: 1.3682x; 1.0043x over previous
#include <cuda_runtime.h>
#include <cstdint>

// v, out: [8, 4096, 16, 64] f32 ; w: [1, 16, 127]
// offset(b,s,h,e) = ((b*4096 + s)*16 + h)*64 + e ; s = s1*64 + s2
#define SSTR   1024
#define NW     127
#define STAGES 8
#define WSTG   1024                 // bytes per warp per stage (8 rows x 128B)
#define STAGEB (8 * WSTG)           // 8 KB per stage

__device__ __forceinline__ void cpasync16(uint32_t dst, const void* src) {
    asm volatile("cp.async.cg.shared.global [%0], [%1], 16;\n"
                 :: "r"(dst), "l"(src));
}
__device__ __forceinline__ void cpcommit() {
    asm volatile("cp.async.commit_group;\n");
}
__device__ __forceinline__ void cpwait6() {
    asm volatile("cp.async.wait_group 6;\n");
}
__device__ __forceinline__ void fma2(unsigned long long& acc,
                                     unsigned long long a,
                                     unsigned long long b) {
    asm("fma.rn.f32x2 %0, %1, %2, %0;" : "+l"(acc) : "l"(a), "l"(b));
}

extern __shared__ char smdyn[];     // STAGES * STAGEB = 64 KB stage ring

// Block = (b, h, e-half). Grid 256, 256 threads (8 warps).
// Warp w is a self-contained cp.async pipeline over rows s2 in [8w, 8w+8).
// v8: (1) the per-stage u shuffle-reduce is deferred one stage so its 52-cyc
// latency overlaps the next stage's wait/LDS; (2) phase 2 uses packed
// fma.rn.f32x2 (halves the FFMA count in the DRAM-idle bubble).
__global__ __launch_bounds__(256, 2)
void fftbias2d_v8(const float* __restrict__ v,
                  const float* __restrict__ wg,
                  float* __restrict__ out) {
    const int bid = blockIdx.x;
    const int eh  = bid & 1;                 // e-half (32 floats)
    const int h   = (bid >> 1) & 15;
    const int b   = bid >> 5;

    const int t  = threadIdx.x;
    const int w  = t >> 5;                   // warp 0..7
    const int l  = t & 31;
    const int rp = l >> 3;                   // row-in-4 (0..3)
    const int e4 = l & 7;                    // float4 within 128B e-half

    __shared__ __align__(16) float4 u_part[16][8][8];  // [ring][w][e4] 16 KB
    __shared__ __align__(16) float4 f_sh[64][8];       // f[s2][e4] -> RxV
    __shared__ __align__(16) float4 u_sh[64][8];       // u[s1][e4] -> RxU
    __shared__ float w_ext[128];

    // K[j][s] = w_ext[j + 64 - s], index in [1,127]; w_ext[127] aliases w[0].
    if (t < NW)  w_ext[t]  = wg[h * NW + t];
    if (t == NW) w_ext[NW] = wg[h * NW];
    __syncthreads();                         // w_ext ready before phase 2

    const float* vb = v + (size_t)b * 4096 * SSTR + h * 64 + eh * 32;
    const uint32_t stg = (uint32_t)__cvta_generic_to_shared(smdyn);

    // Per-warp stage fill: lane l loads rows (8w+rp, 8w+rp+4) at col e4.
    #define ISSUE(s1_) {                                                     \
        const uint32_t _d = stg + ((s1_) & 7) * STAGEB + w * WSTG + l * 16;  \
        const float* _s = vb + (size_t)((s1_) * 64 + 8 * w + rp) * SSTR      \
                             + e4 * 4;                                       \
        cpasync16(_d,       _s);                                             \
        cpasync16(_d + 512, _s + 4 * SSTR);                                  \
        cpcommit();                                                          \
    }

    // Deferred u-partial flush: 2-round shuffle over rp, lanes<8 store.
    #define FLUSH_U(p_, ridx_) {                                             \
        (p_).x += __shfl_xor_sync(0xffffffffu, (p_).x, 8);                   \
        (p_).y += __shfl_xor_sync(0xffffffffu, (p_).y, 8);                   \
        (p_).z += __shfl_xor_sync(0xffffffffu, (p_).z, 8);                   \
        (p_).w += __shfl_xor_sync(0xffffffffu, (p_).w, 8);                   \
        (p_).x += __shfl_xor_sync(0xffffffffu, (p_).x, 16);                  \
        (p_).y += __shfl_xor_sync(0xffffffffu, (p_).y, 16);                  \
        (p_).z += __shfl_xor_sync(0xffffffffu, (p_).z, 16);                  \
        (p_).w += __shfl_xor_sync(0xffffffffu, (p_).w, 16);                  \
        if (l < 8) u_part[(ridx_) & 15][w][l] = (p_);                        \
    }

    #pragma unroll
    for (int s1 = 0; s1 < STAGES - 1; ++s1) ISSUE(s1);

    float4 fa0 = make_float4(0.f, 0.f, 0.f, 0.f);
    float4 fa1 = make_float4(0.f, 0.f, 0.f, 0.f);
    float4 pend = make_float4(0.f, 0.f, 0.f, 0.f);

    for (int grp = 0; grp < 8; ++grp) {
        #pragma unroll
        for (int i = 0; i < 8; ++i) {
            const int s1 = grp * 8 + i;
            cpwait6();                        // this warp's stage s1 resident
            const char* buf = smdyn + (s1 & 7) * STAGEB + w * WSTG + l * 16;
            const float4 a0 = *(const float4*)buf;
            const float4 a1 = *(const float4*)(buf + 512);
            if (s1 + STAGES - 1 < 64) ISSUE(s1 + STAGES - 1) else cpcommit();
            if (i > 0) FLUSH_U(pend, s1 - 1);          // previous stage
            fa0.x += a0.x; fa0.y += a0.y; fa0.z += a0.z; fa0.w += a0.w;
            fa1.x += a1.x; fa1.y += a1.y; fa1.z += a1.z; fa1.w += a1.w;
            pend.x = a0.x + a1.x; pend.y = a0.y + a1.y;
            pend.z = a0.z + a1.z; pend.w = a0.w + a1.w;
        }
        FLUSH_U(pend, grp * 8 + 7);           // peel last stage of the group
        __syncthreads();                      // group's u_part complete
        if (t < 64) {                         // fold 8 warp-partials
            const int s1g = grp * 8 + (t >> 3);
            const int eq  = t & 7;
            float4 a = make_float4(0.f, 0.f, 0.f, 0.f);
            #pragma unroll
            for (int w2 = 0; w2 < 8; ++w2) {
                const float4 p = u_part[s1g & 15][w2][eq];
                a.x += p.x; a.y += p.y; a.z += p.z; a.w += p.w;
            }
            u_sh[s1g][eq] = a;
        }
        // next group writes the other ring parity -> no second barrier
    }
    f_sh[8 * w + rp    ][e4] = fa0;
    f_sh[8 * w + rp + 4][e4] = fa1;
    __syncthreads();

    // ---- Phase 2 (packed f32x2): RxV[j] = sum_s K[j,s] f[s]; RxU likewise.
    // warp = e4 slice (broadcast LDS); lane = j, handles j and j+32.
    {
        ulonglong2 rv0 = {0ull, 0ull}, rv1 = {0ull, 0ull};
        ulonglong2 ru0 = {0ull, 0ull}, ru1 = {0ull, 0ull};
        #pragma unroll 4
        for (int s = 0; s < 64; ++s) {
            const ulonglong2 fv = *(const ulonglong2*)&f_sh[s][w];
            const ulonglong2 uv = *(const ulonglong2*)&u_sh[s][w];
            const float wa = w_ext[l + 64 - s];
            const float wb = w_ext[l + 96 - s];
            unsigned long long wa2, wb2;
            asm("mov.b64 %0, {%1, %1};" : "=l"(wa2) : "r"(__float_as_uint(wa)));
            asm("mov.b64 %0, {%1, %1};" : "=l"(wb2) : "r"(__float_as_uint(wb)));
            fma2(rv0.x, fv.x, wa2);  fma2(rv0.y, fv.y, wa2);
            fma2(rv1.x, fv.x, wb2);  fma2(rv1.y, fv.y, wb2);
            fma2(ru0.x, uv.x, wa2);  fma2(ru0.y, uv.y, wa2);
            fma2(ru1.x, uv.x, wb2);  fma2(ru1.y, uv.y, wb2);
        }
        __syncthreads();
        *(ulonglong2*)&f_sh[l     ][w] = rv0;   // f_sh now holds RxV
        *(ulonglong2*)&f_sh[l + 32][w] = rv1;
        *(ulonglong2*)&u_sh[l     ][w] = ru0;   // u_sh now holds RxU
        *(ulonglong2*)&u_sh[l + 32][w] = ru1;
    }
    __syncthreads();

    // ---- Phase 3: out[s1*64+s2] = RxV[s2] + RxU[s1]; 4-full-line STG.128.
    {
        const int s2a = 4 * w + rp;
        const float4 rva = f_sh[s2a     ][e4];
        const float4 rvb = f_sh[s2a + 32][e4];
        float* ob = out + (size_t)b * 4096 * SSTR + h * 64 + eh * 32 + e4 * 4;
        #pragma unroll 4
        for (int s1 = 0; s1 < 64; ++s1) {
            const float4 ru = u_sh[s1][e4];  // broadcast
            float* r = ob + (size_t)(s1 * 64) * SSTR;
            float4 o0, o1;
            o0.x = rva.x + ru.x; o0.y = rva.y + ru.y;
            o0.z = rva.z + ru.z; o0.w = rva.w + ru.w;
            o1.x = rvb.x + ru.x; o1.y = rvb.y + ru.y;
            o1.z = rvb.z + ru.z; o1.w = rvb.w + ru.w;
            *(float4*)(r + (size_t)s2a * SSTR)        = o0;
            *(float4*)(r + (size_t)(s2a + 32) * SSTR) = o1;
        }
    }
}

extern "C" void kernel_launch(void* const* d_in, const int* in_sizes, int n_in,
                              void* d_out, int out_size) {
    (void)in_sizes; (void)n_in; (void)out_size;
    const float* v = (const float*)d_in[0];
    const float* w = (const float*)d_in[1];
    float* o = (float*)d_out;
    cudaFuncSetAttribute(fftbias2d_v8,
                         cudaFuncAttributeMaxDynamicSharedMemorySize,
                         STAGES * STAGEB);
    fftbias2d_v8<<<256, 256, STAGES * STAGEB>>>(v, w, o);
}